// round 1
// baseline (speedup 1.0000x reference)
#include <cuda_runtime.h>
#include <cuda_bf16.h>
#include <cstdint>

// NonLocalBlock: B=4, C=64, Ci=32, H=W=64, N=4096
// z = supp + W( softmax_n(theta(supp)^T phi(ref)) @ g(ref) ) + wb
//
// Pipeline:
//  prep : theta/phi/g projections (fp32 math, bf16 outputs) into scratch
//  pass1: colsum[m] = sum_n exp(f[n,m]) (no max-sub needed; f bounded ~|6|); store reciprocal
//  pass2: x1[n,ci] = sum_m exp(f[n,m])*colinv[m]*g[ci,m]; fused epilogue z = supp + x1*W^T + wb
// All GEMMs via mma.sync.m16n8k16 bf16 with fp32 accumulation.

#define B_ 4
#define C_ 64
#define CI 32
#define N_ 4096

typedef __nv_bfloat16 bf16;

// scratch (static device arrays; no runtime allocation)
__device__ __align__(16) bf16 g_theta[B_ * N_ * CI];   // [b][n][ci]
__device__ __align__(16) bf16 g_phi[B_ * N_ * CI];     // [b][m][ci]
__device__ __align__(16) bf16 g_gy[B_ * CI * N_];      // [b][ci][m]
__device__ __align__(16) float g_colinv[B_ * N_];      // [b][m]

__device__ __forceinline__ uint32_t pack_bf2(float x, float y) {
    __nv_bfloat162 h = __float22bfloat162_rn(make_float2(x, y));
    return *reinterpret_cast<uint32_t*>(&h);
}

__device__ __forceinline__ void mma16816(float* c, const uint32_t* a, const uint32_t* b) {
    asm volatile(
        "mma.sync.aligned.m16n8k16.row.col.f32.bf16.bf16.f32 "
        "{%0,%1,%2,%3}, {%4,%5,%6,%7}, {%8,%9}, {%0,%1,%2,%3};\n"
        : "+f"(c[0]), "+f"(c[1]), "+f"(c[2]), "+f"(c[3])
        : "r"(a[0]), "r"(a[1]), "r"(a[2]), "r"(a[3]), "r"(b[0]), "r"(b[1]));
}

// ---------------------------------------------------------------------------
// prep: projections. grid (N/128, B), block 128. One n per thread.
// ---------------------------------------------------------------------------
__global__ __launch_bounds__(128) void prep_kernel(
    const float* __restrict__ supp, const float* __restrict__ ref,
    const float* __restrict__ tw, const float* __restrict__ tb,
    const float* __restrict__ pw, const float* __restrict__ pb,
    const float* __restrict__ gw, const float* __restrict__ gb) {
    __shared__ float stw[CI * C_], spw[CI * C_], sgw[CI * C_];
    __shared__ float stb[CI], spb[CI], sgb[CI];
    int tid = threadIdx.x;
    for (int i = tid; i < CI * C_; i += 128) {
        stw[i] = tw[i]; spw[i] = pw[i]; sgw[i] = gw[i];
    }
    if (tid < CI) { stb[tid] = tb[tid]; spb[tid] = pb[tid]; sgb[tid] = gb[tid]; }
    __syncthreads();

    int b = blockIdx.y;
    int n = blockIdx.x * 128 + tid;
    const float* sp = supp + (size_t)b * C_ * N_ + n;
    const float* rf = ref + (size_t)b * C_ * N_ + n;

    // theta from supp
    {
        float acc[CI];
#pragma unroll
        for (int i = 0; i < CI; i++) acc[i] = stb[i];
        for (int c = 0; c < C_; c++) {
            float v = sp[(size_t)c * N_];
#pragma unroll
            for (int i = 0; i < CI; i++) acc[i] += stw[i * C_ + c] * v;
        }
        uint32_t* dst = (uint32_t*)(g_theta + ((size_t)b * N_ + n) * CI);
#pragma unroll
        for (int i = 0; i < CI / 2; i++) dst[i] = pack_bf2(acc[2 * i], acc[2 * i + 1]);
    }
    // phi + g from ref
    {
        float accp[CI], accg[CI];
#pragma unroll
        for (int i = 0; i < CI; i++) { accp[i] = spb[i]; accg[i] = sgb[i]; }
        for (int c = 0; c < C_; c++) {
            float v = rf[(size_t)c * N_];
#pragma unroll
            for (int i = 0; i < CI; i++) {
                accp[i] += spw[i * C_ + c] * v;
                accg[i] += sgw[i * C_ + c] * v;
            }
        }
        uint32_t* dst = (uint32_t*)(g_phi + ((size_t)b * N_ + n) * CI);
#pragma unroll
        for (int i = 0; i < CI / 2; i++) dst[i] = pack_bf2(accp[2 * i], accp[2 * i + 1]);
#pragma unroll
        for (int i = 0; i < CI; i++)
            g_gy[(size_t)b * CI * N_ + (size_t)i * N_ + n] = __float2bfloat16(accg[i]);
    }
}

// ---------------------------------------------------------------------------
// pass1: column sums of exp(f) over n. grid (N/64 m-tiles, B), block 128 (4 warps).
// Each block owns 64 m columns (phi B-fragments pinned in registers), loops n tiles.
// ---------------------------------------------------------------------------
__global__ __launch_bounds__(128) void pass1_kernel() {
    __shared__ __align__(16) bf16 At[64 * 40];  // theta tile, padded stride 40 (conflict-free)
    __shared__ float cs[64];
    int tid = threadIdx.x;
    int lane = tid & 31, w = tid >> 5;
    int g = lane >> 2, tg = lane & 3;
    int b = blockIdx.y;
    int m0 = blockIdx.x * 64;
    const bf16* thB = g_theta + (size_t)b * N_ * CI;
    const bf16* phB = g_phi + (size_t)b * N_ * CI;

    // B fragments (phi), fixed for whole block
    uint32_t bfr[8][2][2];
#pragma unroll
    for (int j = 0; j < 8; j++)
#pragma unroll
        for (int kk = 0; kk < 2; kk++) {
            const bf16* p = phB + (size_t)(m0 + j * 8 + g) * CI + kk * 16 + tg * 2;
            bfr[j][kk][0] = *(const uint32_t*)p;
            bfr[j][kk][1] = *(const uint32_t*)(p + 8);
        }
    float part[16];
#pragma unroll
    for (int i = 0; i < 16; i++) part[i] = 0.f;
    if (tid < 64) cs[tid] = 0.f;

    for (int nt = 0; nt < 64; ++nt) {
        __syncthreads();
        {
            const uint4* src = (const uint4*)(thB + (size_t)nt * 64 * CI);
#pragma unroll
            for (int k = 0; k < 2; k++) {
                int idx = tid + k * 128;
                int r = idx >> 2, q = idx & 3;
                *(uint4*)(At + r * 40 + q * 8) = src[idx];
            }
        }
        __syncthreads();
        uint32_t a[2][4];
        const bf16* Ar = At + (w * 16) * 40;
#pragma unroll
        for (int kk = 0; kk < 2; kk++) {
            a[kk][0] = *(const uint32_t*)(Ar + g * 40 + kk * 16 + tg * 2);
            a[kk][1] = *(const uint32_t*)(Ar + (g + 8) * 40 + kk * 16 + tg * 2);
            a[kk][2] = *(const uint32_t*)(Ar + g * 40 + kk * 16 + tg * 2 + 8);
            a[kk][3] = *(const uint32_t*)(Ar + (g + 8) * 40 + kk * 16 + tg * 2 + 8);
        }
#pragma unroll
        for (int j = 0; j < 8; j++) {
            float c[4] = {0.f, 0.f, 0.f, 0.f};
            mma16816(c, a[0], bfr[j][0]);
            mma16816(c, a[1], bfr[j][1]);
            part[j * 2] += __expf(c[0]) + __expf(c[2]);
            part[j * 2 + 1] += __expf(c[1]) + __expf(c[3]);
        }
    }
    // reduce over g (lanes stride 4)
#pragma unroll
    for (int off = 4; off <= 16; off <<= 1)
#pragma unroll
        for (int i = 0; i < 16; i++) part[i] += __shfl_xor_sync(0xffffffffu, part[i], off);
    __syncthreads();
    if (g == 0) {
#pragma unroll
        for (int j = 0; j < 8; j++) {
            atomicAdd(&cs[j * 8 + tg * 2], part[j * 2]);
            atomicAdd(&cs[j * 8 + tg * 2 + 1], part[j * 2 + 1]);
        }
    }
    __syncthreads();
    if (tid < 64) g_colinv[(size_t)b * N_ + m0 + tid] = 1.0f / cs[tid];
}

// ---------------------------------------------------------------------------
// pass2: x1 = P @ g^T, fused residual conv epilogue.
// grid (N/64 n-tiles, B), block 128 (4 warps, warp w owns rows w*16..+15).
// P never touches smem: exp'd S C-fragments ARE valid A-fragments.
// ---------------------------------------------------------------------------
__global__ __launch_bounds__(128) void pass2_kernel(
    const float* __restrict__ supp, const float* __restrict__ ww,
    const float* __restrict__ wb, float* __restrict__ zout) {
    __shared__ __align__(16) bf16 Ph[64 * 40];  // phi tile   [m][ci] pad 40
    __shared__ __align__(16) bf16 Gt[32 * 72];  // g tile     [ci][m] pad 72
    __shared__ __align__(16) bf16 Ws[64 * 40];  // w weights  [c][ci] pad 40
    __shared__ float cv[64];
    __shared__ float wbs[64];
    int tid = threadIdx.x;
    int lane = tid & 31, w = tid >> 5;
    int g = lane >> 2, tg = lane & 3;
    int b = blockIdx.y;
    int n0 = blockIdx.x * 64;
    const bf16* thB = g_theta + (size_t)b * N_ * CI;
    const bf16* phB = g_phi + (size_t)b * N_ * CI;
    const bf16* gB = g_gy + (size_t)b * CI * N_;
    const float* cinv = g_colinv + (size_t)b * N_;

    for (int i = tid; i < C_ * CI; i += 128)
        Ws[(i >> 5) * 40 + (i & 31)] = __float2bfloat16(ww[i]);
    if (tid < 64) wbs[tid] = wb[tid];

    // A fragments (theta), fixed for block lifetime
    uint32_t a[2][4];
    {
        const bf16* Ar = thB + (size_t)(n0 + w * 16) * CI;
#pragma unroll
        for (int kk = 0; kk < 2; kk++) {
            a[kk][0] = *(const uint32_t*)(Ar + (size_t)g * CI + kk * 16 + tg * 2);
            a[kk][1] = *(const uint32_t*)(Ar + (size_t)(g + 8) * CI + kk * 16 + tg * 2);
            a[kk][2] = *(const uint32_t*)(Ar + (size_t)g * CI + kk * 16 + tg * 2 + 8);
            a[kk][3] = *(const uint32_t*)(Ar + (size_t)(g + 8) * CI + kk * 16 + tg * 2 + 8);
        }
    }
    float x1[4][4];
#pragma unroll
    for (int i = 0; i < 4; i++)
#pragma unroll
        for (int k = 0; k < 4; k++) x1[i][k] = 0.f;

    for (int mt = 0; mt < 64; ++mt) {
        int m0 = mt * 64;
        __syncthreads();
        {
            const uint4* srcP = (const uint4*)(phB + (size_t)m0 * CI);
#pragma unroll
            for (int k = 0; k < 2; k++) {
                int idx = tid + k * 128;
                int r = idx >> 2, q = idx & 3;
                *(uint4*)(Ph + r * 40 + q * 8) = srcP[idx];
            }
#pragma unroll
            for (int k = 0; k < 2; k++) {
                int idx = tid + k * 128;
                int r = idx >> 3, q = idx & 7;
                *(uint4*)(Gt + r * 72 + q * 8) = *(const uint4*)(gB + (size_t)r * N_ + m0 + q * 8);
            }
            if (tid < 64) cv[tid] = cinv[m0 + tid];
        }
        __syncthreads();
        // gemm1: S = theta_tile * phi_tile^T, then P = exp(S)*colinv -> A frags
        uint32_t ap[4][4];
#pragma unroll
        for (int j = 0; j < 8; j++) {
            uint32_t bp[2][2];
#pragma unroll
            for (int kk = 0; kk < 2; kk++) {
                const bf16* p = Ph + (j * 8 + g) * 40 + kk * 16 + tg * 2;
                bp[kk][0] = *(const uint32_t*)p;
                bp[kk][1] = *(const uint32_t*)(p + 8);
            }
            float c[4] = {0.f, 0.f, 0.f, 0.f};
            mma16816(c, a[0], bp[0]);
            mma16816(c, a[1], bp[1]);
            float2 cvp = *(const float2*)&cv[j * 8 + tg * 2];
            float p0 = __expf(c[0]) * cvp.x;
            float p1 = __expf(c[1]) * cvp.y;
            float p2 = __expf(c[2]) * cvp.x;
            float p3 = __expf(c[3]) * cvp.y;
            int kt = j >> 1;
            int o = (j & 1) ? 2 : 0;
            ap[kt][o] = pack_bf2(p0, p1);
            ap[kt][o + 1] = pack_bf2(p2, p3);
        }
        // gemm2: x1[n][ci] += P[n][m] * g[ci][m]
#pragma unroll
        for (int cc = 0; cc < 4; cc++) {
#pragma unroll
            for (int kt = 0; kt < 4; kt++) {
                uint32_t bg[2];
                const bf16* p = Gt + (cc * 8 + g) * 72 + kt * 16 + tg * 2;
                bg[0] = *(const uint32_t*)p;
                bg[1] = *(const uint32_t*)(p + 8);
                mma16816(x1[cc], ap[kt], bg);
            }
        }
    }
    // epilogue: z[n][c] = supp + x1[n][:] * Ws[c][:] + wb[c]
    uint32_t ax[2][4];
#pragma unroll
    for (int cc = 0; cc < 4; cc++) {
        int kt = cc >> 1;
        int o = (cc & 1) ? 2 : 0;
        ax[kt][o] = pack_bf2(x1[cc][0], x1[cc][1]);
        ax[kt][o + 1] = pack_bf2(x1[cc][2], x1[cc][3]);
    }
#pragma unroll
    for (int cc2 = 0; cc2 < 8; cc2++) {
        float zc[4] = {0.f, 0.f, 0.f, 0.f};
#pragma unroll
        for (int kk = 0; kk < 2; kk++) {
            uint32_t bw[2];
            const bf16* p = Ws + (cc2 * 8 + g) * 40 + kk * 16 + tg * 2;
            bw[0] = *(const uint32_t*)p;
            bw[1] = *(const uint32_t*)(p + 8);
            mma16816(zc, ax[kk], bw);
        }
        int c = cc2 * 8 + tg * 2;
        int n = n0 + w * 16 + g;
        size_t base = ((size_t)b * C_ + c) * N_ + n;
        zout[base] = zc[0] + wbs[c] + supp[base];
        zout[base + N_] = zc[1] + wbs[c + 1] + supp[base + N_];
        zout[base + 8] = zc[2] + wbs[c] + supp[base + 8];
        zout[base + N_ + 8] = zc[3] + wbs[c + 1] + supp[base + N_ + 8];
    }
}

extern "C" void kernel_launch(void* const* d_in, const int* in_sizes, int n_in,
                              void* d_out, int out_size) {
    const float* supp = (const float*)d_in[0];
    const float* ref = (const float*)d_in[1];
    const float* tw = (const float*)d_in[2];
    const float* tb = (const float*)d_in[3];
    const float* pw = (const float*)d_in[4];
    const float* pb = (const float*)d_in[5];
    const float* gw = (const float*)d_in[6];
    const float* gb = (const float*)d_in[7];
    const float* ww = (const float*)d_in[8];
    const float* wb = (const float*)d_in[9];
    float* z = (float*)d_out;

    prep_kernel<<<dim3(N_ / 128, B_), 128>>>(supp, ref, tw, tb, pw, pb, gw, gb);
    pass1_kernel<<<dim3(N_ / 64, B_), 128>>>();
    pass2_kernel<<<dim3(N_ / 64, B_), 128>>>(supp, ww, wb, z);
}

// round 2
// speedup vs baseline: 1.2623x; 1.2623x over previous
#include <cuda_runtime.h>
#include <cuda_bf16.h>
#include <cstdint>

// NonLocalBlock: B=4, C=64, Ci=32, H=W=64, N=4096
// z = supp + W( softmax_n(theta(supp)^T phi(ref)) @ g(ref) ) + wb
//
// Pipeline:
//  prep : theta/phi/g projections (fp32 math, bf16 outputs), one projection per
//         blockIdx.z slice for occupancy; c-loop batched x8 for MLP
//  pass1: colsum[m] = sum_n exp(f[n,m]) (no max-sub needed; f bounded ~|6|); store reciprocal
//  pass2: x1[n,ci] = sum_m exp(f[n,m])*colinv[m]*g[ci,m]; fused epilogue z = supp + x1*W^T + wb
// All GEMMs via mma.sync.m16n8k16 bf16 with fp32 accumulation.

#define B_ 4
#define C_ 64
#define CI 32
#define N_ 4096

typedef __nv_bfloat16 bf16;

// scratch (static device arrays; no runtime allocation)
__device__ __align__(16) bf16 g_theta[B_ * N_ * CI];   // [b][n][ci]
__device__ __align__(16) bf16 g_phi[B_ * N_ * CI];     // [b][m][ci]
__device__ __align__(16) bf16 g_gy[B_ * CI * N_];      // [b][ci][m]
__device__ __align__(16) float g_colinv[B_ * N_];      // [b][m]

__device__ __forceinline__ uint32_t pack_bf2(float x, float y) {
    __nv_bfloat162 h = __float22bfloat162_rn(make_float2(x, y));
    return *reinterpret_cast<uint32_t*>(&h);
}

__device__ __forceinline__ void mma16816(float* c, const uint32_t* a, const uint32_t* b) {
    asm volatile(
        "mma.sync.aligned.m16n8k16.row.col.f32.bf16.bf16.f32 "
        "{%0,%1,%2,%3}, {%4,%5,%6,%7}, {%8,%9}, {%0,%1,%2,%3};\n"
        : "+f"(c[0]), "+f"(c[1]), "+f"(c[2]), "+f"(c[3])
        : "r"(a[0]), "r"(a[1]), "r"(a[2]), "r"(a[3]), "r"(b[0]), "r"(b[1]));
}

// ---------------------------------------------------------------------------
// prep: projections. grid (N/256, B, 3), block 256. One n per thread,
// one projection per z-slice (0=theta from supp, 1=phi from ref, 2=g from ref).
// c-loop processed in batches of 8 loads for MLP.
// ---------------------------------------------------------------------------
__global__ __launch_bounds__(256) void prep_kernel(
    const float* __restrict__ supp, const float* __restrict__ ref,
    const float* __restrict__ tw, const float* __restrict__ tb,
    const float* __restrict__ pw, const float* __restrict__ pb,
    const float* __restrict__ gw, const float* __restrict__ gb) {
    __shared__ float sw[CI * C_];
    __shared__ float sb[CI];
    int tid = threadIdx.x;
    int z = blockIdx.z;
    const float* wsel = (z == 0) ? tw : (z == 1) ? pw : gw;
    const float* bsel = (z == 0) ? tb : (z == 1) ? pb : gb;
    const float* xsel = (z == 0) ? supp : ref;
    for (int i = tid; i < CI * C_; i += 256) sw[i] = wsel[i];
    if (tid < CI) sb[tid] = bsel[tid];
    __syncthreads();

    int b = blockIdx.y;
    int n = blockIdx.x * 256 + tid;
    const float* xp = xsel + (size_t)b * C_ * N_ + n;

    float acc[CI];
#pragma unroll
    for (int i = 0; i < CI; i++) acc[i] = sb[i];

#pragma unroll
    for (int c0 = 0; c0 < C_; c0 += 8) {
        float v[8];
#pragma unroll
        for (int k = 0; k < 8; k++) v[k] = xp[(size_t)(c0 + k) * N_];
#pragma unroll
        for (int k = 0; k < 8; k++) {
#pragma unroll
            for (int i = 0; i < CI; i++) acc[i] += sw[i * C_ + c0 + k] * v[k];
        }
    }

    if (z == 0) {
        uint32_t* dst = (uint32_t*)(g_theta + ((size_t)b * N_ + n) * CI);
#pragma unroll
        for (int i = 0; i < CI / 2; i++) dst[i] = pack_bf2(acc[2 * i], acc[2 * i + 1]);
    } else if (z == 1) {
        uint32_t* dst = (uint32_t*)(g_phi + ((size_t)b * N_ + n) * CI);
#pragma unroll
        for (int i = 0; i < CI / 2; i++) dst[i] = pack_bf2(acc[2 * i], acc[2 * i + 1]);
    } else {
#pragma unroll
        for (int i = 0; i < CI; i++)
            g_gy[(size_t)b * CI * N_ + (size_t)i * N_ + n] = __float2bfloat16(acc[i]);
    }
}

// ---------------------------------------------------------------------------
// pass1: column sums of exp(f) over n. grid (N/64 m-tiles, B), block 128 (4 warps).
// Each block owns 64 m columns (phi B-fragments pinned in registers), loops n tiles.
// ---------------------------------------------------------------------------
__global__ __launch_bounds__(128) void pass1_kernel() {
    __shared__ __align__(16) bf16 At[64 * 40];  // theta tile, padded stride 40 (conflict-free)
    __shared__ float cs[64];
    int tid = threadIdx.x;
    int lane = tid & 31, w = tid >> 5;
    int g = lane >> 2, tg = lane & 3;
    int b = blockIdx.y;
    int m0 = blockIdx.x * 64;
    const bf16* thB = g_theta + (size_t)b * N_ * CI;
    const bf16* phB = g_phi + (size_t)b * N_ * CI;

    // B fragments (phi), fixed for whole block
    uint32_t bfr[8][2][2];
#pragma unroll
    for (int j = 0; j < 8; j++)
#pragma unroll
        for (int kk = 0; kk < 2; kk++) {
            const bf16* p = phB + (size_t)(m0 + j * 8 + g) * CI + kk * 16 + tg * 2;
            bfr[j][kk][0] = *(const uint32_t*)p;
            bfr[j][kk][1] = *(const uint32_t*)(p + 8);
        }
    float part[16];
#pragma unroll
    for (int i = 0; i < 16; i++) part[i] = 0.f;
    if (tid < 64) cs[tid] = 0.f;

    for (int nt = 0; nt < 64; ++nt) {
        __syncthreads();
        {
            const uint4* src = (const uint4*)(thB + (size_t)nt * 64 * CI);
#pragma unroll
            for (int k = 0; k < 2; k++) {
                int idx = tid + k * 128;
                int r = idx >> 2, q = idx & 3;
                *(uint4*)(At + r * 40 + q * 8) = src[idx];
            }
        }
        __syncthreads();
        uint32_t a[2][4];
        const bf16* Ar = At + (w * 16) * 40;
#pragma unroll
        for (int kk = 0; kk < 2; kk++) {
            a[kk][0] = *(const uint32_t*)(Ar + g * 40 + kk * 16 + tg * 2);
            a[kk][1] = *(const uint32_t*)(Ar + (g + 8) * 40 + kk * 16 + tg * 2);
            a[kk][2] = *(const uint32_t*)(Ar + g * 40 + kk * 16 + tg * 2 + 8);
            a[kk][3] = *(const uint32_t*)(Ar + (g + 8) * 40 + kk * 16 + tg * 2 + 8);
        }
#pragma unroll
        for (int j = 0; j < 8; j++) {
            float c[4] = {0.f, 0.f, 0.f, 0.f};
            mma16816(c, a[0], bfr[j][0]);
            mma16816(c, a[1], bfr[j][1]);
            part[j * 2] += __expf(c[0]) + __expf(c[2]);
            part[j * 2 + 1] += __expf(c[1]) + __expf(c[3]);
        }
    }
    // reduce over g (lanes stride 4)
#pragma unroll
    for (int off = 4; off <= 16; off <<= 1)
#pragma unroll
        for (int i = 0; i < 16; i++) part[i] += __shfl_xor_sync(0xffffffffu, part[i], off);
    __syncthreads();
    if (g == 0) {
#pragma unroll
        for (int j = 0; j < 8; j++) {
            atomicAdd(&cs[j * 8 + tg * 2], part[j * 2]);
            atomicAdd(&cs[j * 8 + tg * 2 + 1], part[j * 2 + 1]);
        }
    }
    __syncthreads();
    if (tid < 64) g_colinv[(size_t)b * N_ + m0 + tid] = 1.0f / cs[tid];
}

// ---------------------------------------------------------------------------
// pass2: x1 = P @ g^T, fused residual conv epilogue.
// grid (N/64 n-tiles, B), block 128 (4 warps, warp w owns rows w*16..+15).
// P never touches smem: exp'd S C-fragments ARE valid A-fragments.
// ---------------------------------------------------------------------------
__global__ __launch_bounds__(128) void pass2_kernel(
    const float* __restrict__ supp, const float* __restrict__ ww,
    const float* __restrict__ wb, float* __restrict__ zout) {
    __shared__ __align__(16) bf16 Ph[64 * 40];  // phi tile   [m][ci] pad 40
    __shared__ __align__(16) bf16 Gt[32 * 72];  // g tile     [ci][m] pad 72
    __shared__ __align__(16) bf16 Ws[64 * 40];  // w weights  [c][ci] pad 40
    __shared__ float cv[64];
    __shared__ float wbs[64];
    int tid = threadIdx.x;
    int lane = tid & 31, w = tid >> 5;
    int g = lane >> 2, tg = lane & 3;
    int b = blockIdx.y;
    int n0 = blockIdx.x * 64;
    const bf16* thB = g_theta + (size_t)b * N_ * CI;
    const bf16* phB = g_phi + (size_t)b * N_ * CI;
    const bf16* gB = g_gy + (size_t)b * CI * N_;
    const float* cinv = g_colinv + (size_t)b * N_;

    for (int i = tid; i < C_ * CI; i += 128)
        Ws[(i >> 5) * 40 + (i & 31)] = __float2bfloat16(ww[i]);
    if (tid < 64) wbs[tid] = wb[tid];

    // A fragments (theta), fixed for block lifetime
    uint32_t a[2][4];
    {
        const bf16* Ar = thB + (size_t)(n0 + w * 16) * CI;
#pragma unroll
        for (int kk = 0; kk < 2; kk++) {
            a[kk][0] = *(const uint32_t*)(Ar + (size_t)g * CI + kk * 16 + tg * 2);
            a[kk][1] = *(const uint32_t*)(Ar + (size_t)(g + 8) * CI + kk * 16 + tg * 2);
            a[kk][2] = *(const uint32_t*)(Ar + (size_t)g * CI + kk * 16 + tg * 2 + 8);
            a[kk][3] = *(const uint32_t*)(Ar + (size_t)(g + 8) * CI + kk * 16 + tg * 2 + 8);
        }
    }
    float x1[4][4];
#pragma unroll
    for (int i = 0; i < 4; i++)
#pragma unroll
        for (int k = 0; k < 4; k++) x1[i][k] = 0.f;

    for (int mt = 0; mt < 64; ++mt) {
        int m0 = mt * 64;
        __syncthreads();
        {
            const uint4* srcP = (const uint4*)(phB + (size_t)m0 * CI);
#pragma unroll
            for (int k = 0; k < 2; k++) {
                int idx = tid + k * 128;
                int r = idx >> 2, q = idx & 3;
                *(uint4*)(Ph + r * 40 + q * 8) = srcP[idx];
            }
#pragma unroll
            for (int k = 0; k < 2; k++) {
                int idx = tid + k * 128;
                int r = idx >> 3, q = idx & 7;
                *(uint4*)(Gt + r * 72 + q * 8) = *(const uint4*)(gB + (size_t)r * N_ + m0 + q * 8);
            }
            if (tid < 64) cv[tid] = cinv[m0 + tid];
        }
        __syncthreads();
        // gemm1: S = theta_tile * phi_tile^T, then P = exp(S)*colinv -> A frags
        uint32_t ap[4][4];
#pragma unroll
        for (int j = 0; j < 8; j++) {
            uint32_t bp[2][2];
#pragma unroll
            for (int kk = 0; kk < 2; kk++) {
                const bf16* p = Ph + (j * 8 + g) * 40 + kk * 16 + tg * 2;
                bp[kk][0] = *(const uint32_t*)p;
                bp[kk][1] = *(const uint32_t*)(p + 8);
            }
            float c[4] = {0.f, 0.f, 0.f, 0.f};
            mma16816(c, a[0], bp[0]);
            mma16816(c, a[1], bp[1]);
            float2 cvp = *(const float2*)&cv[j * 8 + tg * 2];
            float p0 = __expf(c[0]) * cvp.x;
            float p1 = __expf(c[1]) * cvp.y;
            float p2 = __expf(c[2]) * cvp.x;
            float p3 = __expf(c[3]) * cvp.y;
            int kt = j >> 1;
            int o = (j & 1) ? 2 : 0;
            ap[kt][o] = pack_bf2(p0, p1);
            ap[kt][o + 1] = pack_bf2(p2, p3);
        }
        // gemm2: x1[n][ci] += P[n][m] * g[ci][m]
#pragma unroll
        for (int cc = 0; cc < 4; cc++) {
#pragma unroll
            for (int kt = 0; kt < 4; kt++) {
                uint32_t bg[2];
                const bf16* p = Gt + (cc * 8 + g) * 72 + kt * 16 + tg * 2;
                bg[0] = *(const uint32_t*)p;
                bg[1] = *(const uint32_t*)(p + 8);
                mma16816(x1[cc], ap[kt], bg);
            }
        }
    }
    // epilogue: z[n][c] = supp + x1[n][:] * Ws[c][:] + wb[c]
    uint32_t ax[2][4];
#pragma unroll
    for (int cc = 0; cc < 4; cc++) {
        int kt = cc >> 1;
        int o = (cc & 1) ? 2 : 0;
        ax[kt][o] = pack_bf2(x1[cc][0], x1[cc][1]);
        ax[kt][o + 1] = pack_bf2(x1[cc][2], x1[cc][3]);
    }
#pragma unroll
    for (int cc2 = 0; cc2 < 8; cc2++) {
        float zc[4] = {0.f, 0.f, 0.f, 0.f};
#pragma unroll
        for (int kk = 0; kk < 2; kk++) {
            uint32_t bw[2];
            const bf16* p = Ws + (cc2 * 8 + g) * 40 + kk * 16 + tg * 2;
            bw[0] = *(const uint32_t*)p;
            bw[1] = *(const uint32_t*)(p + 8);
            mma16816(zc, ax[kk], bw);
        }
        int c = cc2 * 8 + tg * 2;
        int n = n0 + w * 16 + g;
        size_t base = ((size_t)b * C_ + c) * N_ + n;
        zout[base] = zc[0] + wbs[c] + supp[base];
        zout[base + N_] = zc[1] + wbs[c + 1] + supp[base + N_];
        zout[base + 8] = zc[2] + wbs[c] + supp[base + 8];
        zout[base + N_ + 8] = zc[3] + wbs[c + 1] + supp[base + N_ + 8];
    }
}

extern "C" void kernel_launch(void* const* d_in, const int* in_sizes, int n_in,
                              void* d_out, int out_size) {
    const float* supp = (const float*)d_in[0];
    const float* ref = (const float*)d_in[1];
    const float* tw = (const float*)d_in[2];
    const float* tb = (const float*)d_in[3];
    const float* pw = (const float*)d_in[4];
    const float* pb = (const float*)d_in[5];
    const float* gw = (const float*)d_in[6];
    const float* gb = (const float*)d_in[7];
    const float* ww = (const float*)d_in[8];
    const float* wb = (const float*)d_in[9];
    float* z = (float*)d_out;

    prep_kernel<<<dim3(N_ / 256, B_, 3), 256>>>(supp, ref, tw, tb, pw, pb, gw, gb);
    pass1_kernel<<<dim3(N_ / 64, B_), 128>>>();
    pass2_kernel<<<dim3(N_ / 64, B_), 128>>>(supp, ww, wb, z);
}

// round 3
// speedup vs baseline: 1.9118x; 1.5145x over previous
#include <cuda_runtime.h>
#include <cuda_bf16.h>
#include <cstdint>

// NonLocalBlock: B=4, C=64, Ci=32, H=W=64, N=4096
// z = supp + W( softmax_n(theta(supp)^T phi(ref)) @ g(ref) ) + wb
//
//  prep : projections, 6-way split (3 proj x 2 output halves) for occupancy
//  pass1: colsum[m] = sum_n exp(f[n,m]); 256-thr blocks, cp.async double-buffer
//  pass2: x1 = P @ g^T with warps split over m-halves; fused residual epilogue
// All GEMMs via mma.sync.m16n8k16 bf16 / fp32 accum. No max-subtraction needed
// (f bounded ~|6| given 0.05-scaled weights; softmax shift-invariant).

#define B_ 4
#define C_ 64
#define CI 32
#define N_ 4096

typedef __nv_bfloat16 bf16;

__device__ __align__(16) bf16 g_theta[B_ * N_ * CI];   // [b][n][ci]
__device__ __align__(16) bf16 g_phi[B_ * N_ * CI];     // [b][m][ci]
__device__ __align__(16) bf16 g_gy[B_ * CI * N_];      // [b][ci][m]
__device__ __align__(16) float g_colinv[B_ * N_];      // [b][m]

__device__ __forceinline__ uint32_t pack_bf2(float x, float y) {
    __nv_bfloat162 h = __float22bfloat162_rn(make_float2(x, y));
    return *reinterpret_cast<uint32_t*>(&h);
}

__device__ __forceinline__ void mma16816(float* c, const uint32_t* a, const uint32_t* b) {
    asm volatile(
        "mma.sync.aligned.m16n8k16.row.col.f32.bf16.bf16.f32 "
        "{%0,%1,%2,%3}, {%4,%5,%6,%7}, {%8,%9}, {%0,%1,%2,%3};\n"
        : "+f"(c[0]), "+f"(c[1]), "+f"(c[2]), "+f"(c[3])
        : "r"(a[0]), "r"(a[1]), "r"(a[2]), "r"(a[3]), "r"(b[0]), "r"(b[1]));
}

__device__ __forceinline__ void cp16(void* dst, const void* src) {
    uint32_t s = (uint32_t)__cvta_generic_to_shared(dst);
    asm volatile("cp.async.cg.shared.global [%0], [%1], 16;\n" :: "r"(s), "l"(src));
}
#define CP_COMMIT asm volatile("cp.async.commit_group;\n")
#define CP_WAIT0  asm volatile("cp.async.wait_group 0;\n")

// ---------------------------------------------------------------------------
// prep: grid (N/256, B, 6), block 256. z = proj*2 + half; 16 outputs/thread.
// ---------------------------------------------------------------------------
__global__ __launch_bounds__(256) void prep_kernel(
    const float* __restrict__ supp, const float* __restrict__ ref,
    const float* __restrict__ tw, const float* __restrict__ tb,
    const float* __restrict__ pw, const float* __restrict__ pb,
    const float* __restrict__ gw, const float* __restrict__ gb) {
    __shared__ float sw[16 * C_];
    __shared__ float sb[16];
    int tid = threadIdx.x;
    int z = blockIdx.z;
    int proj = z >> 1, half = z & 1;
    const float* wsel = (proj == 0) ? tw : (proj == 1) ? pw : gw;
    const float* bsel = (proj == 0) ? tb : (proj == 1) ? pb : gb;
    const float* xsel = (proj == 0) ? supp : ref;
    for (int i = tid; i < 16 * C_; i += 256) sw[i] = wsel[half * 16 * C_ + i];
    if (tid < 16) sb[tid] = bsel[half * 16 + tid];
    __syncthreads();

    int b = blockIdx.y;
    int n = blockIdx.x * 256 + tid;
    const float* xp = xsel + (size_t)b * C_ * N_ + n;

    float acc[16];
#pragma unroll
    for (int i = 0; i < 16; i++) acc[i] = sb[i];
#pragma unroll
    for (int c0 = 0; c0 < C_; c0 += 8) {
        float v[8];
#pragma unroll
        for (int k = 0; k < 8; k++) v[k] = xp[(size_t)(c0 + k) * N_];
#pragma unroll
        for (int k = 0; k < 8; k++)
#pragma unroll
            for (int i = 0; i < 16; i++) acc[i] += sw[i * C_ + c0 + k] * v[k];
    }

    if (proj < 2) {
        bf16* base = (proj == 0) ? g_theta : g_phi;
        uint32_t* dst = (uint32_t*)(base + (size_t)b * N_ * CI) + (size_t)n * 16 + half * 8;
#pragma unroll
        for (int i = 0; i < 8; i++) dst[i] = pack_bf2(acc[2 * i], acc[2 * i + 1]);
    } else {
#pragma unroll
        for (int i = 0; i < 16; i++)
            g_gy[(size_t)b * CI * N_ + (size_t)(half * 16 + i) * N_ + n] = __float2bfloat16(acc[i]);
    }
}

// ---------------------------------------------------------------------------
// pass1: grid (N/64 m-tiles, B), block 256 (8 warps x 16 rows = 128-row chunk).
// Double-buffered theta tile via cp.async.
// ---------------------------------------------------------------------------
__global__ __launch_bounds__(256) void pass1_kernel() {
    __shared__ __align__(16) bf16 At[2][128 * 40];
    __shared__ float cs[64];
    int tid = threadIdx.x;
    int lane = tid & 31, w = tid >> 5;
    int g = lane >> 2, tg = lane & 3;
    int b = blockIdx.y;
    int m0 = blockIdx.x * 64;
    const bf16* thB = g_theta + (size_t)b * N_ * CI;
    const bf16* phB = g_phi + (size_t)b * N_ * CI;

    // B fragments (phi), fixed for whole block
    uint32_t bfr[8][2][2];
#pragma unroll
    for (int j = 0; j < 8; j++)
#pragma unroll
        for (int kk = 0; kk < 2; kk++) {
            const bf16* p = phB + (size_t)(m0 + j * 8 + g) * CI + kk * 16 + tg * 2;
            bfr[j][kk][0] = *(const uint32_t*)p;
            bfr[j][kk][1] = *(const uint32_t*)(p + 8);
        }
    float part[16];
#pragma unroll
    for (int i = 0; i < 16; i++) part[i] = 0.f;
    if (tid < 64) cs[tid] = 0.f;

    // prologue: tile 0 (512 x 16B chunks, 2 per thread)
    {
        int i0 = tid, i1 = tid + 256;
        cp16(&At[0][(i0 >> 2) * 40 + (i0 & 3) * 8], thB + (size_t)(i0 >> 2) * CI + (i0 & 3) * 8);
        cp16(&At[0][(i1 >> 2) * 40 + (i1 & 3) * 8], thB + (size_t)(i1 >> 2) * CI + (i1 & 3) * 8);
        CP_COMMIT;
    }
    for (int nt = 0; nt < 32; ++nt) {
        CP_WAIT0;
        __syncthreads();
        if (nt + 1 < 32) {
            const bf16* s = thB + (size_t)(nt + 1) * 128 * CI;
            bf16* d = At[(nt + 1) & 1];
            int i0 = tid, i1 = tid + 256;
            cp16(&d[(i0 >> 2) * 40 + (i0 & 3) * 8], s + (size_t)(i0 >> 2) * CI + (i0 & 3) * 8);
            cp16(&d[(i1 >> 2) * 40 + (i1 & 3) * 8], s + (size_t)(i1 >> 2) * CI + (i1 & 3) * 8);
            CP_COMMIT;
        }
        uint32_t a[2][4];
        const bf16* Ar = At[nt & 1] + (w * 16) * 40;
#pragma unroll
        for (int kk = 0; kk < 2; kk++) {
            a[kk][0] = *(const uint32_t*)(Ar + g * 40 + kk * 16 + tg * 2);
            a[kk][1] = *(const uint32_t*)(Ar + (g + 8) * 40 + kk * 16 + tg * 2);
            a[kk][2] = *(const uint32_t*)(Ar + g * 40 + kk * 16 + tg * 2 + 8);
            a[kk][3] = *(const uint32_t*)(Ar + (g + 8) * 40 + kk * 16 + tg * 2 + 8);
        }
#pragma unroll
        for (int j = 0; j < 8; j++) {
            float c[4] = {0.f, 0.f, 0.f, 0.f};
            mma16816(c, a[0], bfr[j][0]);
            mma16816(c, a[1], bfr[j][1]);
            part[j * 2] += __expf(c[0]) + __expf(c[2]);
            part[j * 2 + 1] += __expf(c[1]) + __expf(c[3]);
        }
        __syncthreads();
    }
    // reduce over g within warp (lanes stride 4), then atomic into cs
#pragma unroll
    for (int off = 4; off <= 16; off <<= 1)
#pragma unroll
        for (int i = 0; i < 16; i++) part[i] += __shfl_xor_sync(0xffffffffu, part[i], off);
    if (g == 0) {
#pragma unroll
        for (int j = 0; j < 8; j++) {
            atomicAdd(&cs[j * 8 + tg * 2], part[j * 2]);
            atomicAdd(&cs[j * 8 + tg * 2 + 1], part[j * 2 + 1]);
        }
    }
    __syncthreads();
    if (tid < 64) g_colinv[(size_t)b * N_ + m0 + tid] = 1.0f / cs[tid];
}

// ---------------------------------------------------------------------------
// pass2: grid (N/64 n-tiles, B), block 256 (8 warps). Warp w: row-group wq=w&3
// (rows n0+wq*16), m-half mh=w>>2 of a 128-wide m tile. Double-buffered
// phi / g / colinv tiles via cp.async; cross-half x1 reduction via smem
// aliased over the dead Ph buffer; fused residual-conv epilogue.
// ---------------------------------------------------------------------------
#define GTS 136  // Gt row stride (128 + 8 pad), 16B-aligned, conflict-free

__global__ __launch_bounds__(256) void pass2_kernel(
    const float* __restrict__ supp, const float* __restrict__ ww,
    const float* __restrict__ wb, float* __restrict__ zout) {
    __shared__ __align__(16) bf16 Ph[2][128 * 40];   // [m][ci] pad 40
    __shared__ __align__(16) bf16 Gt[2][32 * GTS];   // [ci][m] pad GTS
    __shared__ __align__(16) bf16 Ws[64 * 40];       // [c][ci]
    __shared__ float cvb[2][128];
    __shared__ float wbs[64];
    int tid = threadIdx.x;
    int lane = tid & 31, w = tid >> 5;
    int wq = w & 3, mh = w >> 2;
    int g = lane >> 2, tg = lane & 3;
    int b = blockIdx.y;
    int n0 = blockIdx.x * 64;
    const bf16* thB = g_theta + (size_t)b * N_ * CI;
    const bf16* phB = g_phi + (size_t)b * N_ * CI;
    const bf16* gB = g_gy + (size_t)b * CI * N_;
    const float* cinv = g_colinv + (size_t)b * N_;

    for (int i = tid; i < C_ * CI; i += 256)
        Ws[(i >> 5) * 40 + (i & 31)] = __float2bfloat16(ww[i]);
    if (tid < 64) wbs[tid] = wb[tid];

    // A fragments (theta rows n0 + wq*16), fixed for block lifetime
    uint32_t a[2][4];
    {
        const bf16* Ar = thB + (size_t)(n0 + wq * 16) * CI;
#pragma unroll
        for (int kk = 0; kk < 2; kk++) {
            a[kk][0] = *(const uint32_t*)(Ar + (size_t)g * CI + kk * 16 + tg * 2);
            a[kk][1] = *(const uint32_t*)(Ar + (size_t)(g + 8) * CI + kk * 16 + tg * 2);
            a[kk][2] = *(const uint32_t*)(Ar + (size_t)g * CI + kk * 16 + tg * 2 + 8);
            a[kk][3] = *(const uint32_t*)(Ar + (size_t)(g + 8) * CI + kk * 16 + tg * 2 + 8);
        }
    }
    float x1[4][4];
#pragma unroll
    for (int i = 0; i < 4; i++)
#pragma unroll
        for (int k = 0; k < 4; k++) x1[i][k] = 0.f;

    // tile issue: 128 m-rows of phi (512 chunks) + 32x128 g (512 chunks) + cv
    auto issue = [&](int mt, int bufi) {
        const bf16* ps = phB + (size_t)mt * 128 * CI;
        const bf16* gs = gB + (size_t)mt * 128;
        int i0 = tid, i1 = tid + 256;
        cp16(&Ph[bufi][(i0 >> 2) * 40 + (i0 & 3) * 8], ps + (size_t)(i0 >> 2) * CI + (i0 & 3) * 8);
        cp16(&Ph[bufi][(i1 >> 2) * 40 + (i1 & 3) * 8], ps + (size_t)(i1 >> 2) * CI + (i1 & 3) * 8);
        cp16(&Gt[bufi][(i0 >> 4) * GTS + (i0 & 15) * 8], gs + (size_t)(i0 >> 4) * N_ + (i0 & 15) * 8);
        cp16(&Gt[bufi][(i1 >> 4) * GTS + (i1 & 15) * 8], gs + (size_t)(i1 >> 4) * N_ + (i1 & 15) * 8);
        if (tid < 32) cp16(&cvb[bufi][tid * 4], cinv + (size_t)mt * 128 + tid * 4);
    };

    issue(0, 0);
    CP_COMMIT;
    for (int mt = 0; mt < 32; ++mt) {
        CP_WAIT0;
        __syncthreads();
        if (mt + 1 < 32) { issue(mt + 1, (mt + 1) & 1); CP_COMMIT; }
        int bufi = mt & 1;
        // gemm1: S = theta * phi^T (this warp's 64-col m-half), P = exp(S)*colinv
        uint32_t ap[4][4];
#pragma unroll
        for (int j = 0; j < 8; j++) {
            int pr = mh * 64 + j * 8 + g;
            uint32_t bp[2][2];
#pragma unroll
            for (int kk = 0; kk < 2; kk++) {
                const bf16* p = Ph[bufi] + pr * 40 + kk * 16 + tg * 2;
                bp[kk][0] = *(const uint32_t*)p;
                bp[kk][1] = *(const uint32_t*)(p + 8);
            }
            float c[4] = {0.f, 0.f, 0.f, 0.f};
            mma16816(c, a[0], bp[0]);
            mma16816(c, a[1], bp[1]);
            float2 cvp = *(const float2*)&cvb[bufi][mh * 64 + j * 8 + tg * 2];
            float p0 = __expf(c[0]) * cvp.x;
            float p1 = __expf(c[1]) * cvp.y;
            float p2 = __expf(c[2]) * cvp.x;
            float p3 = __expf(c[3]) * cvp.y;
            int kt = j >> 1;
            int o = (j & 1) ? 2 : 0;
            ap[kt][o] = pack_bf2(p0, p1);
            ap[kt][o + 1] = pack_bf2(p2, p3);
        }
        // gemm2: x1[n][ci] += P[n][m-half] * g[ci][m-half]
#pragma unroll
        for (int cc = 0; cc < 4; cc++) {
#pragma unroll
            for (int kt = 0; kt < 4; kt++) {
                uint32_t bg[2];
                const bf16* p = Gt[bufi] + (cc * 8 + g) * GTS + mh * 64 + kt * 16 + tg * 2;
                bg[0] = *(const uint32_t*)p;
                bg[1] = *(const uint32_t*)(p + 8);
                mma16816(x1[cc], ap[kt], bg);
            }
        }
        __syncthreads();
    }

    // cross-m-half reduction (alias scratch over dead Ph buffers; stride 17)
    float* xr = (float*)Ph;  // 4 wq * 32 lanes * 17 floats = 8704B < 20KB
    if (mh == 1) {
#pragma unroll
        for (int cc = 0; cc < 4; cc++)
#pragma unroll
            for (int k = 0; k < 4; k++) xr[(wq * 32 + lane) * 17 + cc * 4 + k] = x1[cc][k];
    }
    __syncthreads();
    if (mh == 0) {
#pragma unroll
        for (int cc = 0; cc < 4; cc++)
#pragma unroll
            for (int k = 0; k < 4; k++) x1[cc][k] += xr[(wq * 32 + lane) * 17 + cc * 4 + k];

        // epilogue: z[n][c] = supp + x1[n][:] * Ws[c][:] + wb[c]
        uint32_t ax[2][4];
#pragma unroll
        for (int cc = 0; cc < 4; cc++) {
            int kt = cc >> 1;
            int o = (cc & 1) ? 2 : 0;
            ax[kt][o] = pack_bf2(x1[cc][0], x1[cc][1]);
            ax[kt][o + 1] = pack_bf2(x1[cc][2], x1[cc][3]);
        }
#pragma unroll
        for (int cc2 = 0; cc2 < 8; cc2++) {
            float zc[4] = {0.f, 0.f, 0.f, 0.f};
#pragma unroll
            for (int kk = 0; kk < 2; kk++) {
                uint32_t bw[2];
                const bf16* p = Ws + (cc2 * 8 + g) * 40 + kk * 16 + tg * 2;
                bw[0] = *(const uint32_t*)p;
                bw[1] = *(const uint32_t*)(p + 8);
                mma16816(zc, ax[kk], bw);
            }
            int c = cc2 * 8 + tg * 2;
            int n = n0 + wq * 16 + g;
            size_t base = ((size_t)b * C_ + c) * N_ + n;
            zout[base] = zc[0] + wbs[c] + supp[base];
            zout[base + N_] = zc[1] + wbs[c + 1] + supp[base + N_];
            zout[base + 8] = zc[2] + wbs[c] + supp[base + 8];
            zout[base + N_ + 8] = zc[3] + wbs[c + 1] + supp[base + N_ + 8];
        }
    }
}

extern "C" void kernel_launch(void* const* d_in, const int* in_sizes, int n_in,
                              void* d_out, int out_size) {
    const float* supp = (const float*)d_in[0];
    const float* ref = (const float*)d_in[1];
    const float* tw = (const float*)d_in[2];
    const float* tb = (const float*)d_in[3];
    const float* pw = (const float*)d_in[4];
    const float* pb = (const float*)d_in[5];
    const float* gw = (const float*)d_in[6];
    const float* gb = (const float*)d_in[7];
    const float* ww = (const float*)d_in[8];
    const float* wb = (const float*)d_in[9];
    float* z = (float*)d_out;

    prep_kernel<<<dim3(N_ / 256, B_, 6), 256>>>(supp, ref, tw, tb, pw, pb, gw, gb);
    pass1_kernel<<<dim3(N_ / 64, B_), 256>>>();
    pass2_kernel<<<dim3(N_ / 64, B_), 256>>>(supp, ww, wb, z);
}